// round 1
// baseline (speedup 1.0000x reference)
#include <cuda_runtime.h>

// Problem constants
#define BVAL   4
#define LVAL   8
#define CVAL   256
#define SVAL   64
#define WVAL   64
#define BLV    (BVAL*LVAL)      // 32
#define SWV    (SVAL*WVAL)      // 4096
#define NROWS  (BLV*SWV)        // 131072
#define HVAL   4
#define DVAL   64
#define C3     (3*CVAL)         // 768
#define LN_EPS 1e-5f
#define ATTN_SCALE 0.125f       // D^-0.5

// Static device scratch (allocation-free per harness rules)
__device__ float g_xn [(long)NROWS * CVAL];   // LayerNorm output (N, C)
__device__ float g_qkv[(long)NROWS * C3];     // qkv (N, 768) interleaved (d,h,t)
__device__ float g_xa [(long)NROWS * CVAL];   // attention output (N, C) with c = d*4+h

// ---------------------------------------------------------------------------
// Kernel 1: gather-transpose + LayerNorm
// x layout: (BL, C, SW). Each block: one bl, 32 sw positions, all 256 channels.
// ---------------------------------------------------------------------------
__global__ void ln_kernel(const float* __restrict__ x,
                          const float* __restrict__ gamma,
                          const float* __restrict__ beta) {
    __shared__ float tile[CVAL][33];   // padded: bank-conflict-free column reads
    const int bl  = blockIdx.y;
    const int sw0 = blockIdx.x * 32;
    const int tid = threadIdx.x;

    const float* xp = x + ((long)bl * CVAL) * SWV + sw0;
    for (int idx = tid; idx < CVAL * 32; idx += 256) {
        int c = idx >> 5, i = idx & 31;
        tile[c][i] = xp[(long)c * SWV + i];
    }
    __syncthreads();

    const int warp = tid >> 5, lane = tid & 31;
    #pragma unroll
    for (int rr = 0; rr < 4; rr++) {
        const int i = warp * 4 + rr;          // sw within tile
        float s = 0.f, sq = 0.f;
        #pragma unroll
        for (int q = 0; q < 8; q++) {
            float v = tile[lane + 32 * q][i];
            s += v; sq += v * v;
        }
        #pragma unroll
        for (int o = 16; o > 0; o >>= 1) {
            s  += __shfl_xor_sync(0xffffffffu, s,  o);
            sq += __shfl_xor_sync(0xffffffffu, sq, o);
        }
        const float mean = s * (1.f / CVAL);
        const float var  = sq * (1.f / CVAL) - mean * mean;
        const float rstd = rsqrtf(var + LN_EPS);
        float* op = g_xn + (long)(bl * SWV + sw0 + i) * CVAL;
        #pragma unroll
        for (int q = 0; q < 8; q++) {
            const int c = lane + 32 * q;
            op[c] = (tile[c][i] - mean) * rstd * gamma[c] + beta[c];
        }
    }
}

// ---------------------------------------------------------------------------
// Kernels 2 & 4: register-tiled fp32 SGEMM, 128x128 block tile, 8x8 per thread.
//   out[n, c] = sum_k A[n,k] * W[c,k]     (W row-major (NCOL, 256))
// EPI=false: write qkv scratch (row-major NCOL)
// EPI=true : out += shortcut(x) + bias, scattered to (BL, C, SW) layout
// ---------------------------------------------------------------------------
template<int NCOL, bool EPI>
__global__ void __launch_bounds__(256, 2)
sgemm_kernel(const float* __restrict__ W,
             const float* __restrict__ xres,
             const float* __restrict__ bias,
             float* __restrict__ gout) {
    __shared__ float As[8][128];
    __shared__ float Bs[8][128];

    const float* A = EPI ? g_xa : g_xn;

    float acc[8][8];
    #pragma unroll
    for (int i = 0; i < 8; i++)
        #pragma unroll
        for (int j = 0; j < 8; j++) acc[i][j] = 0.f;

    const int tid = threadIdx.x;
    const int tx = tid & 15, ty = tid >> 4;
    const int n0 = blockIdx.x * 128;
    const int c0 = blockIdx.y * 128;

    const int lr = tid >> 1;            // 0..127
    const int lq = (tid & 1) * 4;       // 0 or 4
    const float* Ag = A + (long)(n0 + lr) * CVAL + lq;
    const float* Bg = W + (long)(c0 + lr) * CVAL + lq;

    float4 a4 = *(const float4*)(Ag);
    float4 b4 = *(const float4*)(Bg);

    for (int k0 = 0; k0 < CVAL; k0 += 8) {
        As[lq + 0][lr] = a4.x; As[lq + 1][lr] = a4.y;
        As[lq + 2][lr] = a4.z; As[lq + 3][lr] = a4.w;
        Bs[lq + 0][lr] = b4.x; Bs[lq + 1][lr] = b4.y;
        Bs[lq + 2][lr] = b4.z; Bs[lq + 3][lr] = b4.w;
        __syncthreads();
        if (k0 + 8 < CVAL) {
            a4 = *(const float4*)(Ag + k0 + 8);
            b4 = *(const float4*)(Bg + k0 + 8);
        }
        #pragma unroll
        for (int kk = 0; kk < 8; kk++) {
            float a[8], b[8];
            *(float4*)&a[0] = *(const float4*)&As[kk][ty * 8];
            *(float4*)&a[4] = *(const float4*)&As[kk][ty * 8 + 4];
            *(float4*)&b[0] = *(const float4*)&Bs[kk][tx * 8];
            *(float4*)&b[4] = *(const float4*)&Bs[kk][tx * 8 + 4];
            #pragma unroll
            for (int i = 0; i < 8; i++)
                #pragma unroll
                for (int j = 0; j < 8; j++)
                    acc[i][j] += a[i] * b[j];
        }
        __syncthreads();
    }

    if (!EPI) {
        // qkv scratch write: row-major (N, NCOL)
        #pragma unroll
        for (int i = 0; i < 8; i++) {
            float* op = g_qkv + (long)(n0 + ty * 8 + i) * NCOL + c0 + tx * 8;
            *(float4*)(op)     = make_float4(acc[i][0], acc[i][1], acc[i][2], acc[i][3]);
            *(float4*)(op + 4) = make_float4(acc[i][4], acc[i][5], acc[i][6], acc[i][7]);
        }
    } else {
        // residual + bias + scatter to (BL, C, SW) output layout
        const int bl = n0 >> 12;                 // n0 / 4096
        const int sw = (n0 & 4095) + ty * 8;
        #pragma unroll
        for (int j = 0; j < 8; j++) {
            const int c = c0 + tx * 8 + j;
            const long off = ((long)(bl * CVAL + c)) * SWV + sw;
            const float bj = bias[c];
            float4 s0 = *(const float4*)(xres + off);
            float4 s1 = *(const float4*)(xres + off + 4);
            float4 o0 = make_float4(acc[0][j] + s0.x + bj, acc[1][j] + s0.y + bj,
                                    acc[2][j] + s0.z + bj, acc[3][j] + s0.w + bj);
            float4 o1 = make_float4(acc[4][j] + s1.x + bj, acc[5][j] + s1.y + bj,
                                    acc[6][j] + s1.z + bj, acc[7][j] + s1.w + bj);
            *(float4*)(gout + off)     = o0;
            *(float4*)(gout + off + 4) = o1;
        }
    }
}

// ---------------------------------------------------------------------------
// Kernel 3: tiny per-row 4x4 cross-head attention. One thread per row.
// qkv row layout (768): j = d*12 + h*3 + t, t in {q,k,v}.
// xa row layout (256):  c = d*4 + h.
// ---------------------------------------------------------------------------
__global__ void attn_kernel() {
    const int n = blockIdx.x * blockDim.x + threadIdx.x;
    const float4* r = (const float4*)(g_qkv + (long)n * C3);

    float logit[4][4];
    #pragma unroll
    for (int h = 0; h < 4; h++)
        #pragma unroll
        for (int g = 0; g < 4; g++) logit[h][g] = 0.f;

    // Pass 1: logits over D=64
    for (int d = 0; d < DVAL; d++) {
        float4 f0 = r[d * 3 + 0];
        float4 f1 = r[d * 3 + 1];
        float4 f2 = r[d * 3 + 2];
        float q[4] = {f0.x, f0.w, f1.z, f2.y};
        float k[4] = {f0.y, f1.x, f1.w, f2.z};
        #pragma unroll
        for (int h = 0; h < 4; h++)
            #pragma unroll
            for (int g = 0; g < 4; g++)
                logit[h][g] += q[h] * k[g];
    }

    // Softmax per h over g
    float attnw[4][4];
    #pragma unroll
    for (int h = 0; h < 4; h++) {
        float m = logit[h][0];
        #pragma unroll
        for (int g = 1; g < 4; g++) m = fmaxf(m, logit[h][g]);
        float ssum = 0.f;
        #pragma unroll
        for (int g = 0; g < 4; g++) {
            attnw[h][g] = __expf((logit[h][g] - m) * ATTN_SCALE);
            ssum += attnw[h][g];
        }
        const float inv = 1.f / ssum;
        #pragma unroll
        for (int g = 0; g < 4; g++) attnw[h][g] *= inv;
    }

    // Pass 2: stream v, write xa
    float4* op = (float4*)(g_xa + (long)n * CVAL);
    for (int d = 0; d < DVAL; d++) {
        float4 f0 = r[d * 3 + 0];
        float4 f1 = r[d * 3 + 1];
        float4 f2 = r[d * 3 + 2];
        float v[4] = {f0.z, f1.y, f2.x, f2.w};
        float o[4];
        #pragma unroll
        for (int h = 0; h < 4; h++) {
            o[h] = 0.f;
            #pragma unroll
            for (int g = 0; g < 4; g++) o[h] += attnw[h][g] * v[g];
        }
        op[d] = make_float4(o[0], o[1], o[2], o[3]);
    }
}

// NOTE on softmax scale: reference computes softmax(logit * scale); above we
// apply scale inside exp after subtracting max of UNSCALED logits. Since scale
// is a positive constant, max location is identical and
// exp((l - m)*s) = exp(l*s - m*s): softmax result is identical.

// ---------------------------------------------------------------------------
extern "C" void kernel_launch(void* const* d_in, const int* in_sizes, int n_in,
                              void* d_out, int out_size) {
    const float* x      = (const float*)d_in[0];
    const float* w_qkv  = (const float*)d_in[1];
    const float* w_proj = (const float*)d_in[2];
    const float* b_proj = (const float*)d_in[3];
    const float* gamma  = (const float*)d_in[4];
    const float* beta   = (const float*)d_in[5];
    float* out = (float*)d_out;

    // 1) LayerNorm (transposed gather)
    ln_kernel<<<dim3(SWV / 32, BLV), 256>>>(x, gamma, beta);

    // 2) QKV GEMM: (N,256) @ (256,768)
    sgemm_kernel<C3, false><<<dim3(NROWS / 128, C3 / 128), 256>>>(
        w_qkv, nullptr, nullptr, nullptr);

    // 3) per-row 4x4 attention
    attn_kernel<<<NROWS / 256, 256>>>();

    // 4) proj GEMM + residual + bias + scatter
    sgemm_kernel<CVAL, true><<<dim3(NROWS / 128, CVAL / 128), 256>>>(
        w_proj, x, b_proj, out);
}

// round 8
// speedup vs baseline: 2.2879x; 2.2879x over previous
#include <cuda_runtime.h>
#include <cuda_bf16.h>
#include <cstdint>

#define BLV    32
#define SWV    4096
#define NROWS  131072
#define CVAL   256
#define C3     768
#define LN_EPS 1e-5f
#define ATTN_SCALE 0.125f

// ---------------- static scratch (allocation-free) ----------------
__device__ __nv_bfloat16 g_xn_hi[(size_t)NROWS * CVAL];
__device__ __nv_bfloat16 g_xn_lo[(size_t)NROWS * CVAL];
__device__ __nv_bfloat16 g_xa_hi[(size_t)NROWS * CVAL];
__device__ __nv_bfloat16 g_xa_lo[(size_t)NROWS * CVAL];
__device__ float         g_qkv  [(size_t)NROWS * C3];
__device__ __nv_bfloat16 g_wq_hi[C3 * CVAL],   g_wq_lo[C3 * CVAL];
__device__ __nv_bfloat16 g_wp_hi[CVAL * CVAL], g_wp_lo[CVAL * CVAL];

// ---------------- helpers ----------------
#define SMEM_SWZ(off) ((off) ^ (((off) >> 3) & 0x70))

__device__ __forceinline__ uint32_t smem_u32(const void* p) {
    return (uint32_t)__cvta_generic_to_shared(p);
}

#define CP_ASYNC16(saddr, gptr) \
    asm volatile("cp.async.cg.shared.global [%0], [%1], 16;" \
                 :: "r"(saddr), "l"(__cvta_generic_to_global(gptr)) : "memory")
#define CP_COMMIT() asm volatile("cp.async.commit_group;" ::: "memory")
#define CP_WAIT1()  asm volatile("cp.async.wait_group 1;" ::: "memory")

__device__ __forceinline__ void ldsm_x4(uint32_t* r, uint32_t addr) {
    asm volatile("ldmatrix.sync.aligned.m8n8.x4.shared.b16 {%0,%1,%2,%3}, [%4];"
        : "=r"(r[0]), "=r"(r[1]), "=r"(r[2]), "=r"(r[3]) : "r"(addr));
}

__device__ __forceinline__ void mma16816(float* d, const uint32_t* a, const uint32_t* b) {
    asm volatile("mma.sync.aligned.m16n8k16.row.col.f32.bf16.bf16.f32 "
        "{%0,%1,%2,%3}, {%4,%5,%6,%7}, {%8,%9}, {%0,%1,%2,%3};"
        : "+f"(d[0]), "+f"(d[1]), "+f"(d[2]), "+f"(d[3])
        : "r"(a[0]), "r"(a[1]), "r"(a[2]), "r"(a[3]), "r"(b[0]), "r"(b[1]));
}

__device__ __forceinline__ void split2(float v, __nv_bfloat16& h, __nv_bfloat16& l) {
    h = __float2bfloat16(v);
    l = __float2bfloat16(v - __bfloat162float(h));
}

// ---------------------------------------------------------------------------
// Kernel 0: split fp32 weights into bf16 hi/lo planes
// ---------------------------------------------------------------------------
__global__ void wsplit_kernel(const float* __restrict__ wq, const float* __restrict__ wp) {
    int i = blockIdx.x * 256 + threadIdx.x;
    if (i < C3 * CVAL) {
        __nv_bfloat16 h, l; split2(wq[i], h, l);
        g_wq_hi[i] = h; g_wq_lo[i] = l;
    } else {
        int j = i - C3 * CVAL;
        __nv_bfloat16 h, l; split2(wp[j], h, l);
        g_wp_hi[j] = h; g_wp_lo[j] = l;
    }
}

// ---------------------------------------------------------------------------
// Kernel 1: gather-transpose + LayerNorm -> bf16 hi/lo planes
// ---------------------------------------------------------------------------
__global__ void ln_kernel(const float* __restrict__ x,
                          const float* __restrict__ gamma,
                          const float* __restrict__ beta) {
    __shared__ float tile[CVAL][33];
    const int bl  = blockIdx.y;
    const int sw0 = blockIdx.x * 32;
    const int tid = threadIdx.x;

    const float* xp = x + ((long)bl * CVAL) * SWV + sw0;
    for (int idx = tid; idx < CVAL * 32; idx += 256) {
        int c = idx >> 5, i = idx & 31;
        tile[c][i] = xp[(long)c * SWV + i];
    }
    __syncthreads();

    const int warp = tid >> 5, lane = tid & 31;
    #pragma unroll
    for (int rr = 0; rr < 4; rr++) {
        const int i = warp * 4 + rr;
        float s = 0.f, sq = 0.f;
        #pragma unroll
        for (int q = 0; q < 8; q++) {
            float v = tile[lane + 32 * q][i];
            s += v; sq += v * v;
        }
        #pragma unroll
        for (int o = 16; o > 0; o >>= 1) {
            s  += __shfl_xor_sync(0xffffffffu, s,  o);
            sq += __shfl_xor_sync(0xffffffffu, sq, o);
        }
        const float mean = s * (1.f / CVAL);
        const float var  = sq * (1.f / CVAL) - mean * mean;
        const float rstd = rsqrtf(var + LN_EPS);
        const long rowoff = (long)(bl * SWV + sw0 + i) * CVAL;
        #pragma unroll
        for (int q = 0; q < 8; q++) {
            const int c = lane + 32 * q;
            float v = (tile[c][i] - mean) * rstd * gamma[c] + beta[c];
            __nv_bfloat16 h, l; split2(v, h, l);
            g_xn_hi[rowoff + c] = h;
            g_xn_lo[rowoff + c] = l;
        }
    }
}

// ---------------------------------------------------------------------------
// GEMM: mma.sync bf16 hi/lo-split (3 planes into one fp32 acc).
// CTA tile 128(M rows of activations) x 128(N output channels), K=256.
// 8 warps: 2(M)x4(N), warp tile 64x32, m16n8k16 fragments via ldmatrix.
// K chunks of 64, cp.async double buffer.
// Per buffer: Ah | Al | Wh | Wl, each 128x64 bf16 (16KB, 128B rows, SW128).
// ---------------------------------------------------------------------------
#define GSMEM_BYTES 131072   // 2 x 65536

template<int NTOT, bool EPI>
__global__ void __launch_bounds__(256, 1)
gemm_kernel(const float* __restrict__ bias,
            const float* __restrict__ xres,
            float* __restrict__ out) {
    extern __shared__ char smem[];
    const uint32_t sbase = smem_u32(smem);
    const int tid  = threadIdx.x;
    const int wid  = tid >> 5, lane = tid & 31;
    const int c0   = blockIdx.x * 128;   // output-channel block (fast dim -> L2 A reuse)
    const int n0   = blockIdx.y * 128;   // row block

    const __nv_bfloat16* Ahi = EPI ? g_xa_hi : g_xn_hi;
    const __nv_bfloat16* Alo = EPI ? g_xa_lo : g_xn_lo;
    const __nv_bfloat16* Whi = EPI ? g_wp_hi : g_wq_hi;
    const __nv_bfloat16* Wlo = EPI ? g_wp_lo : g_wq_lo;

    // ---- cp.async producer indexing: row = tid/2, half-row 64B = tid%2 ----
    const int lrow  = tid >> 1;
    const int lhalf = (tid & 1) * 32;            // bf16 element offset in 64-wide row
    uint32_t sw_off[4];
    #pragma unroll
    for (int j = 0; j < 4; j++)
        sw_off[j] = SMEM_SWZ((uint32_t)(lrow * 128 + (tid & 1) * 64 + j * 16));

    const __nv_bfloat16* gsrc[4] = { Ahi + (long)(n0 + lrow) * CVAL + lhalf,
                                     Alo + (long)(n0 + lrow) * CVAL + lhalf,
                                     Whi + (long)(c0 + lrow) * CVAL + lhalf,
                                     Wlo + (long)(c0 + lrow) * CVAL + lhalf };

    auto issue_chunk = [&](int kc, int buf) {
        const uint32_t bb = sbase + buf * 65536;
        #pragma unroll
        for (int t = 0; t < 4; t++) {
            const __nv_bfloat16* gp = gsrc[t] + kc * 64;
            const uint32_t tb = bb + t * 16384;
            #pragma unroll
            for (int j = 0; j < 4; j++)
                CP_ASYNC16(tb + sw_off[j], gp + j * 8);
        }
        CP_COMMIT();
    };

    // ---- fragment addressing (per lane) ----
    const int wm = (wid >> 2) * 64;              // 0 / 64
    const int wn = (wid & 3) * 32;               // 0 / 32 / 64 / 96
    const int a_mo = ((lane >> 3) & 1) * 8 + (lane & 7);
    const int a_kb = (lane >> 4) * 16;
    const int b_no = (lane >> 4) * 8 + (lane & 7);
    const int b_kb = ((lane >> 3) & 1) * 16;
    uint32_t a_rowb[4], b_rowb[2];
    #pragma unroll
    for (int t = 0; t < 4; t++) a_rowb[t] = (uint32_t)((wm + t * 16 + a_mo) * 128);
    #pragma unroll
    for (int u = 0; u < 2; u++) b_rowb[u] = (uint32_t)((wn + u * 16 + b_no) * 128);

    float acc[4][4][4];
    #pragma unroll
    for (int t = 0; t < 4; t++)
        #pragma unroll
        for (int nt = 0; nt < 4; nt++)
            #pragma unroll
            for (int r = 0; r < 4; r++) acc[t][nt][r] = 0.f;

    issue_chunk(0, 0);
    issue_chunk(1, 1);

    for (int kc = 0; kc < 4; kc++) {
        const int buf = kc & 1;
        CP_WAIT1();
        __syncthreads();

        const uint32_t bb = sbase + buf * 65536;
        #pragma unroll
        for (int s = 0; s < 4; s++) {
            uint32_t aoff[4], boff[2];
            #pragma unroll
            for (int t = 0; t < 4; t++)
                aoff[t] = SMEM_SWZ(a_rowb[t] + s * 32 + a_kb);
            #pragma unroll
            for (int u = 0; u < 2; u++)
                boff[u] = SMEM_SWZ(b_rowb[u] + s * 32 + b_kb);

            uint32_t ah[4][4], al[4][4], wh[2][4], wl[2][4];
            #pragma unroll
            for (int t = 0; t < 4; t++) ldsm_x4(ah[t], bb + aoff[t]);            // Ah
            #pragma unroll
            for (int u = 0; u < 2; u++) ldsm_x4(wh[u], bb + 32768 + boff[u]);    // Wh
            #pragma unroll
            for (int t = 0; t < 4; t++) ldsm_x4(al[t], bb + 16384 + aoff[t]);    // Al
            #pragma unroll
            for (int u = 0; u < 2; u++) ldsm_x4(wl[u], bb + 49152 + boff[u]);    // Wl

            #pragma unroll
            for (int t = 0; t < 4; t++)
                #pragma unroll
                for (int nt = 0; nt < 4; nt++) {
                    const uint32_t* bh = &wh[nt >> 1][(nt & 1) * 2];
                    const uint32_t* bl = &wl[nt >> 1][(nt & 1) * 2];
                    mma16816(acc[t][nt], ah[t], bh);   // hi*hi
                    mma16816(acc[t][nt], al[t], bh);   // lo*hi
                    mma16816(acc[t][nt], ah[t], bl);   // hi*lo
                }
        }
        __syncthreads();
        if (kc + 2 < 4) issue_chunk(kc + 2, buf);
    }

    // ---- epilogue ----
    const int ml = lane >> 2;
    const int cl = (lane & 3) * 2;
    if (!EPI) {
        #pragma unroll
        for (int t = 0; t < 4; t++) {
            const long m = n0 + wm + t * 16 + ml;
            float* p0 = g_qkv + m * NTOT + c0 + wn + cl;
            float* p1 = p0 + 8L * NTOT;
            #pragma unroll
            for (int nt = 0; nt < 4; nt++) {
                *(float2*)(p0 + nt * 8) = make_float2(acc[t][nt][0], acc[t][nt][1]);
                *(float2*)(p1 + nt * 8) = make_float2(acc[t][nt][2], acc[t][nt][3]);
            }
        }
    } else {
        const int bl = n0 >> 12;
        const int swb = (n0 & 4095) + wm + ml;
        #pragma unroll
        for (int t = 0; t < 4; t++) {
            const int sw = swb + t * 16;
            #pragma unroll
            for (int nt = 0; nt < 4; nt++) {
                const int c = c0 + wn + nt * 8 + cl;
                const float b0 = bias[c], b1 = bias[c + 1];
                const long o0 = ((long)(bl * 256 + c)) * 4096 + sw;
                const long o1 = o0 + 4096;
                out[o0]     = acc[t][nt][0] + xres[o0]     + b0;
                out[o1]     = acc[t][nt][1] + xres[o1]     + b1;
                out[o0 + 8] = acc[t][nt][2] + xres[o0 + 8] + b0;
                out[o1 + 8] = acc[t][nt][3] + xres[o1 + 8] + b1;
            }
        }
    }
}

// ---------------------------------------------------------------------------
// Kernel 3: warp-per-row 4x4 cross-head attention; reads qkv ONCE.
// ---------------------------------------------------------------------------
__global__ void attn_kernel() {
    const int warp = threadIdx.x >> 5, lane = threadIdx.x & 31;
    const long n = (long)blockIdx.x * 8 + warp;
    const float4* r = (const float4*)(g_qkv + n * C3);

    float4 f[2][3];
    #pragma unroll
    for (int t = 0; t < 2; t++) {
        const int d = lane + t * 32;
        f[t][0] = r[d * 3 + 0];
        f[t][1] = r[d * 3 + 1];
        f[t][2] = r[d * 3 + 2];
    }

    float lg[16];
    #pragma unroll
    for (int e = 0; e < 16; e++) lg[e] = 0.f;
    #pragma unroll
    for (int t = 0; t < 2; t++) {
        float q[4] = {f[t][0].x, f[t][0].w, f[t][1].z, f[t][2].y};
        float k[4] = {f[t][0].y, f[t][1].x, f[t][1].w, f[t][2].z};
        #pragma unroll
        for (int h = 0; h < 4; h++)
            #pragma unroll
            for (int g = 0; g < 4; g++)
                lg[h * 4 + g] += q[h] * k[g];
    }
    #pragma unroll
    for (int e = 0; e < 16; e++)
        #pragma unroll
        for (int o = 16; o > 0; o >>= 1)
            lg[e] += __shfl_xor_sync(0xffffffffu, lg[e], o);

    float aw[16];
    #pragma unroll
    for (int h = 0; h < 4; h++) {
        float mx = lg[h * 4];
        #pragma unroll
        for (int g = 1; g < 4; g++) mx = fmaxf(mx, lg[h * 4 + g]);
        float ssum = 0.f;
        #pragma unroll
        for (int g = 0; g < 4; g++) {
            aw[h * 4 + g] = __expf((lg[h * 4 + g] - mx) * ATTN_SCALE);
            ssum += aw[h * 4 + g];
        }
        const float inv = 1.f / ssum;
        #pragma unroll
        for (int g = 0; g < 4; g++) aw[h * 4 + g] *= inv;
    }

    #pragma unroll
    for (int t = 0; t < 2; t++) {
        const int d = lane + t * 32;
        float v[4] = {f[t][0].z, f[t][1].y, f[t][2].x, f[t][2].w};
        float o[4];
        #pragma unroll
        for (int h = 0; h < 4; h++) {
            o[h] = 0.f;
            #pragma unroll
            for (int g = 0; g < 4; g++) o[h] += aw[h * 4 + g] * v[g];
        }
        __nv_bfloat16 hh[4], ll[4];
        #pragma unroll
        for (int h = 0; h < 4; h++) split2(o[h], hh[h], ll[h]);
        const long off = n * CVAL + d * 4;
        __nv_bfloat162 p;
        p.x = hh[0]; p.y = hh[1]; *(__nv_bfloat162*)(g_xa_hi + off)     = p;
        p.x = hh[2]; p.y = hh[3]; *(__nv_bfloat162*)(g_xa_hi + off + 2) = p;
        p.x = ll[0]; p.y = ll[1]; *(__nv_bfloat162*)(g_xa_lo + off)     = p;
        p.x = ll[2]; p.y = ll[3]; *(__nv_bfloat162*)(g_xa_lo + off + 2) = p;
    }
}

// ---------------------------------------------------------------------------
extern "C" void kernel_launch(void* const* d_in, const int* in_sizes, int n_in,
                              void* d_out, int out_size) {
    const float* x      = (const float*)d_in[0];
    const float* w_qkv  = (const float*)d_in[1];
    const float* w_proj = (const float*)d_in[2];
    const float* b_proj = (const float*)d_in[3];
    const float* gamma  = (const float*)d_in[4];
    const float* beta   = (const float*)d_in[5];
    float* out = (float*)d_out;

    cudaFuncSetAttribute(gemm_kernel<C3, false>,
                         cudaFuncAttributeMaxDynamicSharedMemorySize, GSMEM_BYTES);
    cudaFuncSetAttribute(gemm_kernel<CVAL, true>,
                         cudaFuncAttributeMaxDynamicSharedMemorySize, GSMEM_BYTES);

    // 0) split weights to bf16 hi/lo
    wsplit_kernel<<<(C3 * CVAL + CVAL * CVAL) / 256, 256>>>(w_qkv, w_proj);
    // 1) LayerNorm (transposed gather) -> xn hi/lo planes
    ln_kernel<<<dim3(SWV / 32, BLV), 256>>>(x, gamma, beta);
    // 2) QKV GEMM (mma.sync bf16 split): (N,256)x(256,768) -> g_qkv fp32
    gemm_kernel<C3, false><<<dim3(C3 / 128, NROWS / 128), 256, GSMEM_BYTES>>>(
        nullptr, nullptr, nullptr);
    // 3) warp-per-row attention -> xa hi/lo planes
    attn_kernel<<<NROWS / 8, 256>>>();
    // 4) proj GEMM + residual + bias + scatter to (BL,C,SW)
    gemm_kernel<CVAL, true><<<dim3(CVAL / 128, NROWS / 128), 256, GSMEM_BYTES>>>(
        b_proj, x, out);
}